// round 15
// baseline (speedup 1.0000x reference)
#include <cuda_runtime.h>
#include <cuda_bf16.h>
#include <cuda_fp16.h>
#include <math.h>
#include <stdint.h>

// Problem constants
#define BATCH 8
#define NTOK 1024
#define CDIM 768
#define HEADS 8
#define HD 96
#define MROWS (BATCH * NTOK)   // 8192
#define SCALE_HOST 0.10206207261596577f
#define LOG2E 1.4426950408889634f
#define SOFT_SHIFT 4.0f

// ---------------- scratch (device globals; no allocation allowed) ----------
__device__ __align__(16) __half g_xf16[MROWS * CDIM];
__device__ __align__(16) __half g_yf16[MROWS * CDIM];
__device__ __align__(16) __half g_qf16[MROWS * CDIM];
__device__ __align__(16) __half g_kf16[MROWS * CDIM];
__device__ __align__(16) __half g_vf16[MROWS * CDIM];
__device__ __align__(16) __half g_of16[MROWS * CDIM];
__device__ __align__(16) __half g_wq[CDIM * CDIM];
__device__ __align__(16) __half g_wk[CDIM * CDIM];
__device__ __align__(16) __half g_wv[CDIM * CDIM];
__device__ __align__(16) __half g_wp[CDIM * CDIM];

// ======================= small PTX helpers ===================================
__device__ __forceinline__ uint32_t smem_u32(const void* p) {
    uint32_t a;
    asm("{ .reg .u64 t; cvta.to.shared.u64 t, %1; cvt.u32.u64 %0, t; }"
        : "=r"(a) : "l"(p));
    return a;
}
__device__ __forceinline__ void cp_async16(uint32_t saddr, const void* gaddr) {
    asm volatile("cp.async.cg.shared.global [%0], [%1], 16;"
                 :: "r"(saddr), "l"(gaddr) : "memory");
}
__device__ __forceinline__ void cp_commit() {
    asm volatile("cp.async.commit_group;" ::: "memory");
}
__device__ __forceinline__ void cp_wait_n(int rem) {
    if (rem >= 2)      asm volatile("cp.async.wait_group 2;" ::: "memory");
    else if (rem == 1) asm volatile("cp.async.wait_group 1;" ::: "memory");
    else               asm volatile("cp.async.wait_group 0;" ::: "memory");
}
__device__ __forceinline__ void ldm_x4(uint32_t* r, uint32_t addr) {
    asm volatile("ldmatrix.sync.aligned.m8n8.x4.shared.b16 {%0,%1,%2,%3}, [%4];"
                 : "=r"(r[0]), "=r"(r[1]), "=r"(r[2]), "=r"(r[3]) : "r"(addr));
}
__device__ __forceinline__ void ldm_x4_t(uint32_t* r, uint32_t addr) {
    asm volatile("ldmatrix.sync.aligned.m8n8.x4.trans.shared.b16 {%0,%1,%2,%3}, [%4];"
                 : "=r"(r[0]), "=r"(r[1]), "=r"(r[2]), "=r"(r[3]) : "r"(addr));
}
__device__ __forceinline__ void mma_f16(float* c, const uint32_t* a, const uint32_t* b) {
    asm volatile(
        "mma.sync.aligned.m16n8k16.row.col.f32.f16.f16.f32 "
        "{%0,%1,%2,%3}, {%4,%5,%6,%7}, {%8,%9}, {%0,%1,%2,%3};"
        : "+f"(c[0]), "+f"(c[1]), "+f"(c[2]), "+f"(c[3])
        : "r"(a[0]), "r"(a[1]), "r"(a[2]), "r"(a[3]), "r"(b[0]), "r"(b[1]));
}
__device__ __forceinline__ uint32_t pack_f16(float a, float b) {
    uint32_t r;
    asm("cvt.rn.f16x2.f32 %0, %2, %1;" : "=r"(r) : "f"(a), "f"(b));
    return r;
}
__device__ __forceinline__ uint32_t exp2_pack(float t0, float t1) {
    float p0, p1;
    asm("ex2.approx.f32 %0, %1;" : "=f"(p0) : "f"(t0));
    asm("ex2.approx.f32 %0, %1;" : "=f"(p1) : "f"(t1));
    return pack_f16(p0, p1);
}

// ======================= converts ============================================
__global__ void convert_f16_multi(const float* __restrict__ s0, __half* __restrict__ d0,
                                  const float* __restrict__ s1, __half* __restrict__ d1,
                                  const float* __restrict__ s2, __half* __restrict__ d2,
                                  const float* __restrict__ s3, __half* __restrict__ d3,
                                  int n4)
{
    int i = blockIdx.x * blockDim.x + threadIdx.x;
    if (i >= n4) return;
    const float* src;
    __half* dst;
    switch (blockIdx.z) {
        case 0: src = s0; dst = d0; break;
        case 1: src = s1; dst = d1; break;
        case 2: src = s2; dst = d2; break;
        default: src = s3; dst = d3; break;
    }
    float4 v = reinterpret_cast<const float4*>(src)[i];
    uint32_t h0 = pack_f16(v.x, v.y);
    uint32_t h1 = pack_f16(v.z, v.w);
    reinterpret_cast<uint2*>(dst)[i] = make_uint2(h0, h1);
}

// ======================= 1-pass f16 GEMM (BK=64, 2-stage) ====================
#define BM 128
#define BN 128
#define BK 64
#define NCHUNK (CDIM / BK)       // 12
#define ROWB 144                 // 64 f16 = 128B + 16B pad
#define TILE_SZ (128 * ROWB)     // 18432
#define GSTG (2 * TILE_SZ)       // 36864 per stage (A, W)
#define GEMM_SMEM (2 * GSTG)     // 73728

__device__ __forceinline__ void gemm_body(
    const __half* __restrict__ A, const __half* __restrict__ W,
    const float* __restrict__ bias, float* __restrict__ out32,
    __half* __restrict__ outh, float scale, int mode,
    char* smem, int bm, int bn)
{
    const uint32_t sb = smem_u32(smem);
    const int tid = threadIdx.x;
    const int wid = tid >> 5;
    const int lane = tid & 31;
    const int wm = wid >> 1;
    const int wn = wid & 1;

    const __half* gbase[2];
    gbase[0] = A + (size_t)bm * CDIM;
    gbase[1] = W + (size_t)bn * CDIM;

    float acc[2][8][4];
    #pragma unroll
    for (int i = 0; i < 2; i++)
        #pragma unroll
        for (int j = 0; j < 8; j++)
            #pragma unroll
            for (int q = 0; q < 4; q++) acc[i][j][q] = 0.f;

    auto issue_chunk = [&](int c, int stage) {
        const int k0 = c * BK;
        #pragma unroll
        for (int t = 0; t < 8; t++) {
            int idx = tid + t * 256;          // 0..2047
            int tile = idx >> 10;
            int w = idx & 1023;
            int r = w >> 3, cc = w & 7;
            const __half* gp = gbase[tile] + (size_t)r * CDIM + k0 + cc * 8;
            uint32_t dst = sb + stage * GSTG + tile * TILE_SZ + r * ROWB + cc * 16;
            cp_async16(dst, gp);
        }
        cp_commit();
    };

    issue_chunk(0, 0);

    #pragma unroll 1
    for (int c = 0; c < NCHUNK; c++) {
        // wait for ALL outstanding groups: chunk c is the newest committed here.
        asm volatile("cp.async.wait_group 0;" ::: "memory");
        __syncthreads();
        if (c + 1 < NCHUNK) issue_chunk(c + 1, (c + 1) & 1);

        const uint32_t stg = sb + (c & 1) * GSTG;
        const uint32_t aB = stg;
        const uint32_t bB = stg + TILE_SZ;

        #pragma unroll
        for (int ks = 0; ks < 4; ks++) {
            const int kbyte = ks * 32;

            uint32_t ah[2][4];
            {
                int arow = wm * 32 + (lane & 15);
                int koff = kbyte + ((lane >> 4) << 4);
                #pragma unroll
                for (int i = 0; i < 2; i++) {
                    uint32_t off = (uint32_t)((arow + i * 16) * ROWB + koff);
                    ldm_x4(ah[i], aB + off);
                }
            }

            uint32_t bh[8][2];
            {
                int nrow_in = ((lane >> 4) << 3) + (lane & 7);
                int kadd = ((lane >> 3) & 1) * 16;
                #pragma unroll
                for (int p = 0; p < 4; p++) {
                    int nrow = wn * 64 + p * 16 + nrow_in;
                    uint32_t off = (uint32_t)(nrow * ROWB + kbyte + kadd);
                    uint32_t r4[4];
                    ldm_x4(r4, bB + off);
                    bh[2 * p][0] = r4[0]; bh[2 * p][1] = r4[1];
                    bh[2 * p + 1][0] = r4[2]; bh[2 * p + 1][1] = r4[3];
                }
            }

            #pragma unroll
            for (int i = 0; i < 2; i++)
                #pragma unroll
                for (int j = 0; j < 8; j++)
                    mma_f16(acc[i][j], ah[i], bh[j]);
        }
    }

    const int g = lane >> 2;
    const int tq = lane & 3;
    #pragma unroll
    for (int i = 0; i < 2; i++) {
        #pragma unroll
        for (int j = 0; j < 8; j++) {
            int row = bm + wm * 32 + i * 16 + g;
            int col = bn + wn * 64 + j * 8 + tq * 2;
            if (mode == 0) {
                float b0 = bias ? bias[col] : 0.f;
                float b1 = bias ? bias[col + 1] : 0.f;
                float2 v0 = make_float2(acc[i][j][0] + b0, acc[i][j][1] + b1);
                float2 v1 = make_float2(acc[i][j][2] + b0, acc[i][j][3] + b1);
                *reinterpret_cast<float2*>(out32 + (size_t)row * CDIM + col) = v0;
                *reinterpret_cast<float2*>(out32 + (size_t)(row + 8) * CDIM + col) = v1;
            } else {
                uint32_t h0 = pack_f16(acc[i][j][0] * scale, acc[i][j][1] * scale);
                uint32_t h1 = pack_f16(acc[i][j][2] * scale, acc[i][j][3] * scale);
                *reinterpret_cast<uint32_t*>(outh + (size_t)row * CDIM + col) = h0;
                *reinterpret_cast<uint32_t*>(outh + (size_t)(row + 8) * CDIM + col) = h1;
            }
        }
    }
}

__global__ __launch_bounds__(256, 2) void gemm_qkv(
    const __half* __restrict__ x, const __half* __restrict__ y,
    const __half* __restrict__ wq, const __half* __restrict__ wk,
    const __half* __restrict__ wv,
    __half* __restrict__ qf, __half* __restrict__ kf, __half* __restrict__ vf)
{
    extern __shared__ char smem[];
    const int z = blockIdx.z;
    const __half* A = (z == 0) ? x : y;
    const __half* W = (z == 0) ? wq : (z == 1) ? wk : wv;
    __half* out     = (z == 0) ? qf : (z == 1) ? kf : vf;
    const float scale = (z == 0) ? SCALE_HOST : 1.0f;
    gemm_body(A, W, nullptr, nullptr, out, scale, 1,
              smem, blockIdx.x * BM, blockIdx.y * BN);
}

__global__ __launch_bounds__(256, 2) void gemm_out(
    const __half* __restrict__ A, const __half* __restrict__ W,
    const float* __restrict__ bias, float* __restrict__ out32)
{
    extern __shared__ char smem[];
    gemm_body(A, W, bias, out32, nullptr, 1.0f, 0,
              smem, blockIdx.x * BM, blockIdx.y * BN);
}

// ======================= tensor-core flash attention ========================
// CTA: 128 q rows, 4 warps (32 q-rows each => 2 A-frags). One K/V ldmatrix
// now feeds 4 MMAs (was 2) -> K/V LDSM per MMA halves. 128-thread CTAs at
// 2 CTAs/SM allow up to 255 regs/thread. 4-stage single-sync pipeline.
#define AQ 128
#define AK 32
#define ATHREADS 128
#define QROWB 208
#define NKV (NTOK / AK)          // 32
#define SQ_BYTES (AQ * QROWB)    // 26624
#define KV_BYTES (AK * QROWB)    // 6656
#define ASTG (2 * KV_BYTES)      // 13312 (K, V)
#define ATTN_SMEM (SQ_BYTES + 4 * ASTG)  // 79872

__global__ __launch_bounds__(ATHREADS, 2) void attn_mma(
    const __half* __restrict__ Q_g,
    const __half* __restrict__ K_g,
    const __half* __restrict__ V_g,
    const float* __restrict__ relpos,
    __half* __restrict__ O_g)
{
    extern __shared__ char smem[];
    const uint32_t sb = smem_u32(smem);
    const int tid = threadIdx.x;
    const int lane = tid & 31;
    const int w = tid >> 5;          // 0..3, each owns 32 q rows
    const int g = lane >> 2;
    const int tq = lane & 3;
    const int bh = blockIdx.y;
    const int b = bh >> 3;
    const int h = bh & 7;
    const int q0 = blockIdx.x * AQ;

    const uint32_t sQ = sb;
    const uint32_t sStage = sb + SQ_BYTES;

    const uint32_t ones_b[2] = { (g == 0) ? 0x3C003C00u : 0u,
                                 (g == 0) ? 0x3C003C00u : 0u };

    // ---- load Q tile via cp.async (128 threads x 12 iters = 1536 chunks) ----
    {
        const size_t qb = ((size_t)(b * NTOK + q0)) * CDIM + h * HD;
        #pragma unroll
        for (int t = 0; t < 12; t++) {
            int idx = t * ATHREADS + tid;    // 0..1535
            int r = idx / 12, c = idx % 12;
            uint32_t o = (uint32_t)(r * QROWB + c * 16);
            cp_async16(sQ + o, Q_g + qb + (size_t)r * CDIM + c * 8);
        }
        cp_commit();
    }

    auto load_kv = [&](int kt, int s) {
        const size_t base = ((size_t)(b * NTOK + kt * AK)) * CDIM + h * HD;
        uint32_t st = sStage + s * ASTG;
        #pragma unroll
        for (int t = 0; t < 3; t++) {
            int idx = t * ATHREADS + tid;    // 0..383 = 32*12
            int r = idx / 12, c = idx % 12;
            uint32_t o = (uint32_t)(r * QROWB + c * 16);
            const size_t go = base + (size_t)r * CDIM + c * 8;
            cp_async16(st + o,            K_g + go);
            cp_async16(st + KV_BYTES + o, V_g + go);
        }
        cp_commit();
    };

    load_kv(0, 0);
    load_kv(1, 1);
    load_kv(2, 2);

    asm volatile("cp.async.wait_group 3;" ::: "memory");
    __syncthreads();

    // ---- Q fragments register-resident: 2 m16 tiles x 6 k-steps ----
    uint32_t qreg[2][6][4];
    #pragma unroll
    for (int m = 0; m < 2; m++) {
        const uint32_t aoff =
            (uint32_t)((w * 32 + m * 16 + (lane & 15)) * QROWB + ((lane >> 4) << 4));
        #pragma unroll
        for (int t = 0; t < 6; t++)
            ldm_x4(qreg[m][t], sQ + aoff + t * 32);
    }

    float o[2][12][4];
    float ol[2][4];
    #pragma unroll
    for (int m = 0; m < 2; m++) {
        #pragma unroll
        for (int u = 0; u < 12; u++)
            #pragma unroll
            for (int q = 0; q < 4; q++) o[m][u][q] = 0.f;
        #pragma unroll
        for (int q = 0; q < 4; q++) ol[m][q] = 0.f;
    }

    const float* rpbase = relpos + ((size_t)h * NTOK + q0 + w * 32 + g) * NTOK + tq * 2;

    #pragma unroll 1
    for (int kt = 0; kt < NKV; kt++) {
        cp_wait_n(NKV - 1 - kt);
        __syncthreads();
        if (kt + 3 < NKV) load_kv(kt + 3, (kt + 3) & 3);

        const uint32_t stK = sStage + (kt & 3) * ASTG;
        const uint32_t stV = stK + KV_BYTES;

        // ---- S = Q K^T: one K ldmatrix feeds 4 MMAs (2 m-frags x 2 n8) ----
        float sc[2][4][4];
        #pragma unroll
        for (int m = 0; m < 2; m++)
            #pragma unroll
            for (int j = 0; j < 4; j++)
                #pragma unroll
                for (int q = 0; q < 4; q++) sc[m][j][q] = 0.f;

        {
            const int nr = ((lane >> 4) << 3) + (lane & 7);
            const uint32_t kadd = ((lane >> 3) & 1) << 4;
            #pragma unroll
            for (int t = 0; t < 6; t++) {
                #pragma unroll
                for (int p = 0; p < 2; p++) {
                    uint32_t off = (uint32_t)((16 * p + nr) * QROWB + t * 32 + kadd);
                    uint32_t kh[4];
                    ldm_x4(kh, stK + off);
                    #pragma unroll
                    for (int m = 0; m < 2; m++) {
                        mma_f16(sc[m][2 * p], qreg[m][t], kh);
                        mma_f16(sc[m][2 * p + 1], qreg[m][t], kh + 2);
                    }
                }
            }
        }

        // ---- softmax: P = 2^((S + rp)*L2E - SHIFT*L2E), per m-frag ----
        uint32_t pe[2][4][2];
        #pragma unroll
        for (int m = 0; m < 2; m++) {
            const float* rpb = rpbase + (size_t)(m * 16) * NTOK + kt * AK;
            #pragma unroll
            for (int j = 0; j < 4; j++) {
                float2 r0 = *reinterpret_cast<const float2*>(rpb + (size_t)j * 8);
                float2 r1 = *reinterpret_cast<const float2*>(rpb + 8 * (size_t)NTOK + (size_t)j * 8);
                float t0 = (sc[m][j][0] + r0.x) * LOG2E - SOFT_SHIFT * LOG2E;
                float t1 = (sc[m][j][1] + r0.y) * LOG2E - SOFT_SHIFT * LOG2E;
                float t2 = (sc[m][j][2] + r1.x) * LOG2E - SOFT_SHIFT * LOG2E;
                float t3 = (sc[m][j][3] + r1.y) * LOG2E - SOFT_SHIFT * LOG2E;
                pe[m][j][0] = exp2_pack(t0, t1);
                pe[m][j][1] = exp2_pack(t2, t3);
            }
        }

        // ---- O += P V: one V ldmatrix feeds 4 MMAs; l += P 1 ----
        {
            const int vrow_in = ((lane >> 3) & 1) * 8 + (lane & 7);
            const uint32_t vcb = (uint32_t)((lane >> 4) << 4);
            #pragma unroll
            for (int t = 0; t < 2; t++) {
                uint32_t pa[2][4];
                #pragma unroll
                for (int m = 0; m < 2; m++) {
                    pa[m][0] = pe[m][2 * t][0];
                    pa[m][1] = pe[m][2 * t][1];
                    pa[m][2] = pe[m][2 * t + 1][0];
                    pa[m][3] = pe[m][2 * t + 1][1];
                    mma_f16(ol[m], pa[m], ones_b);
                }
                const uint32_t vro = (uint32_t)((16 * t + vrow_in) * QROWB) + vcb;
                #pragma unroll
                for (int u = 0; u < 6; u++) {
                    uint32_t off = vro + u * 32;
                    uint32_t vh[4];
                    ldm_x4_t(vh, stV + off);
                    #pragma unroll
                    for (int m = 0; m < 2; m++) {
                        mma_f16(o[m][2 * u], pa[m], vh);
                        mma_f16(o[m][2 * u + 1], pa[m], vh + 2);
                    }
                }
            }
        }
    }

    // ---- finalize per m-frag ----
    #pragma unroll
    for (int m = 0; m < 2; m++) {
        float l0 = __shfl_sync(0xffffffffu, ol[m][0], lane & 28);
        float l1 = __shfl_sync(0xffffffffu, ol[m][2], lane & 28);
        const float i0 = 1.f / l0, i1 = 1.f / l1;

        const size_t r0 = (size_t)(b * NTOK + q0 + w * 32 + m * 16 + g) * CDIM;
        const size_t r1 = r0 + 8 * CDIM;
        #pragma unroll
        for (int u = 0; u < 12; u++) {
            const int col = h * HD + u * 8 + tq * 2;
            *reinterpret_cast<uint32_t*>(O_g + r0 + col) =
                pack_f16(o[m][u][0] * i0, o[m][u][1] * i0);
            *reinterpret_cast<uint32_t*>(O_g + r1 + col) =
                pack_f16(o[m][u][2] * i1, o[m][u][3] * i1);
        }
    }
}

// ---------------- launch ----------------------------------------------------
extern "C" void kernel_launch(void* const* d_in, const int* in_sizes, int n_in,
                              void* d_out, int out_size)
{
    const float* x      = (const float*)d_in[0];
    const float* y      = (const float*)d_in[1];
    const float* relpos = (const float*)d_in[2];
    const float* Wq = (const float*)d_in[5];
    const float* Wk = (const float*)d_in[6];
    const float* Wv = (const float*)d_in[7];
    const float* Wp = (const float*)d_in[8];
    const float* bp = (const float*)d_in[9];
    float* out = (float*)d_out;

    __half *xf, *yf, *qf, *kf, *vf, *of;
    __half *wq, *wk, *wv, *wp;
    cudaGetSymbolAddress((void**)&xf, g_xf16);
    cudaGetSymbolAddress((void**)&yf, g_yf16);
    cudaGetSymbolAddress((void**)&qf, g_qf16);
    cudaGetSymbolAddress((void**)&kf, g_kf16);
    cudaGetSymbolAddress((void**)&vf, g_vf16);
    cudaGetSymbolAddress((void**)&of, g_of16);
    cudaGetSymbolAddress((void**)&wq, g_wq);
    cudaGetSymbolAddress((void**)&wk, g_wk);
    cudaGetSymbolAddress((void**)&wv, g_wv);
    cudaGetSymbolAddress((void**)&wp, g_wp);

    const int nBig4 = MROWS * CDIM / 4;
    const int nW4   = CDIM * CDIM / 4;

    {
        dim3 gz((nBig4 + 255) / 256, 1, 2);
        convert_f16_multi<<<gz, 256>>>(x, xf, y, yf, nullptr, nullptr,
                                       nullptr, nullptr, nBig4);
        dim3 gw((nW4 + 255) / 256, 1, 4);
        convert_f16_multi<<<gw, 256>>>(Wq, wq, Wk, wk, Wv, wv, Wp, wp, nW4);
    }

    cudaFuncSetAttribute(gemm_qkv, cudaFuncAttributeMaxDynamicSharedMemorySize, GEMM_SMEM);
    cudaFuncSetAttribute(gemm_out, cudaFuncAttributeMaxDynamicSharedMemorySize, GEMM_SMEM);

    dim3 gqkv(MROWS / BM, CDIM / BN, 3);   // (64, 6, 3) = 1152 CTAs
    gemm_qkv<<<gqkv, 256, GEMM_SMEM>>>(xf, yf, wq, wk, wv, qf, kf, vf);

    cudaFuncSetAttribute(attn_mma, cudaFuncAttributeMaxDynamicSharedMemorySize, ATTN_SMEM);
    dim3 agrid(NTOK / AQ, BATCH * HEADS);  // (8, 64)
    attn_mma<<<agrid, ATHREADS, ATTN_SMEM>>>(qf, kf, vf, relpos, of);

    dim3 gout(MROWS / BM, CDIM / BN);      // (64, 6)
    gemm_out<<<gout, 256, GEMM_SMEM>>>(of, wp, bp, out);
}

// round 16
// speedup vs baseline: 1.0703x; 1.0703x over previous
#include <cuda_runtime.h>
#include <cuda_bf16.h>
#include <cuda_fp16.h>
#include <math.h>
#include <stdint.h>

// Problem constants
#define BATCH 8
#define NTOK 1024
#define CDIM 768
#define HEADS 8
#define HD 96
#define MROWS (BATCH * NTOK)   // 8192
#define SCALE_HOST 0.10206207261596577f
#define LOG2E 1.4426950408889634f
#define SOFT_SHIFT 4.0f

// ---------------- scratch (device globals; no allocation allowed) ----------
__device__ __align__(16) __half g_xf16[MROWS * CDIM];
__device__ __align__(16) __half g_yf16[MROWS * CDIM];
__device__ __align__(16) __half g_qf16[MROWS * CDIM];
__device__ __align__(16) __half g_kf16[MROWS * CDIM];
__device__ __align__(16) __half g_vf16[MROWS * CDIM];
__device__ __align__(16) __half g_of16[MROWS * CDIM];
__device__ __align__(16) __half g_wq[CDIM * CDIM];
__device__ __align__(16) __half g_wk[CDIM * CDIM];
__device__ __align__(16) __half g_wv[CDIM * CDIM];
__device__ __align__(16) __half g_wp[CDIM * CDIM];

// ======================= small PTX helpers ===================================
__device__ __forceinline__ uint32_t smem_u32(const void* p) {
    uint32_t a;
    asm("{ .reg .u64 t; cvta.to.shared.u64 t, %1; cvt.u32.u64 %0, t; }"
        : "=r"(a) : "l"(p));
    return a;
}
__device__ __forceinline__ void cp_async16(uint32_t saddr, const void* gaddr) {
    asm volatile("cp.async.cg.shared.global [%0], [%1], 16;"
                 :: "r"(saddr), "l"(gaddr) : "memory");
}
__device__ __forceinline__ void cp_commit() {
    asm volatile("cp.async.commit_group;" ::: "memory");
}
__device__ __forceinline__ void cp_wait_n(int rem) {
    if (rem >= 2)      asm volatile("cp.async.wait_group 2;" ::: "memory");
    else if (rem == 1) asm volatile("cp.async.wait_group 1;" ::: "memory");
    else               asm volatile("cp.async.wait_group 0;" ::: "memory");
}
__device__ __forceinline__ void ldm_x4(uint32_t* r, uint32_t addr) {
    asm volatile("ldmatrix.sync.aligned.m8n8.x4.shared.b16 {%0,%1,%2,%3}, [%4];"
                 : "=r"(r[0]), "=r"(r[1]), "=r"(r[2]), "=r"(r[3]) : "r"(addr));
}
__device__ __forceinline__ void ldm_x4_t(uint32_t* r, uint32_t addr) {
    asm volatile("ldmatrix.sync.aligned.m8n8.x4.trans.shared.b16 {%0,%1,%2,%3}, [%4];"
                 : "=r"(r[0]), "=r"(r[1]), "=r"(r[2]), "=r"(r[3]) : "r"(addr));
}
__device__ __forceinline__ void mma_f16(float* c, const uint32_t* a, const uint32_t* b) {
    asm volatile(
        "mma.sync.aligned.m16n8k16.row.col.f32.f16.f16.f32 "
        "{%0,%1,%2,%3}, {%4,%5,%6,%7}, {%8,%9}, {%0,%1,%2,%3};"
        : "+f"(c[0]), "+f"(c[1]), "+f"(c[2]), "+f"(c[3])
        : "r"(a[0]), "r"(a[1]), "r"(a[2]), "r"(a[3]), "r"(b[0]), "r"(b[1]));
}
__device__ __forceinline__ uint32_t pack_f16(float a, float b) {
    uint32_t r;
    asm("cvt.rn.f16x2.f32 %0, %2, %1;" : "=r"(r) : "f"(a), "f"(b));
    return r;
}
__device__ __forceinline__ uint32_t exp2_pack(float t0, float t1) {
    float p0, p1;
    asm("ex2.approx.f32 %0, %1;" : "=f"(p0) : "f"(t0));
    asm("ex2.approx.f32 %0, %1;" : "=f"(p1) : "f"(t1));
    return pack_f16(p0, p1);
}

// ======================= converts ============================================
__global__ void convert_f16_multi(const float* __restrict__ s0, __half* __restrict__ d0,
                                  const float* __restrict__ s1, __half* __restrict__ d1,
                                  const float* __restrict__ s2, __half* __restrict__ d2,
                                  const float* __restrict__ s3, __half* __restrict__ d3,
                                  int n4)
{
    int i = blockIdx.x * blockDim.x + threadIdx.x;
    if (i >= n4) return;
    const float* src;
    __half* dst;
    switch (blockIdx.z) {
        case 0: src = s0; dst = d0; break;
        case 1: src = s1; dst = d1; break;
        case 2: src = s2; dst = d2; break;
        default: src = s3; dst = d3; break;
    }
    float4 v = reinterpret_cast<const float4*>(src)[i];
    uint32_t h0 = pack_f16(v.x, v.y);
    uint32_t h1 = pack_f16(v.z, v.w);
    reinterpret_cast<uint2*>(dst)[i] = make_uint2(h0, h1);
}

// ======================= 1-pass f16 GEMM (BK=64, 2-stage) ====================
// Templated on W tile rows (BN): WROWS=128 (qkv) or 64 (out-proj, finer waves).
#define BM 128
#define BK 64
#define NCHUNK (CDIM / BK)       // 12
#define ROWB 144                 // 64 f16 = 128B + 16B pad
#define TILE_A (128 * ROWB)      // 18432

template<int WROWS>
__device__ __forceinline__ void gemm_body(
    const __half* __restrict__ A, const __half* __restrict__ W,
    const float* __restrict__ bias, float* __restrict__ out32,
    __half* __restrict__ outh, float scale, int mode,
    char* smem, int bm, int bn)
{
    constexpr int JT = WROWS / 16;           // n8 tiles per warp (8 or 4)
    constexpr int TILE_W = WROWS * ROWB;
    constexpr int GSTG = TILE_A + TILE_W;
    const uint32_t sb = smem_u32(smem);
    const int tid = threadIdx.x;
    const int wid = tid >> 5;
    const int lane = tid & 31;
    const int wm = wid >> 1;
    const int wn = wid & 1;

    const __half* Abase = A + (size_t)bm * CDIM;
    const __half* Wbase = W + (size_t)bn * CDIM;

    float acc[2][JT][4];
    #pragma unroll
    for (int i = 0; i < 2; i++)
        #pragma unroll
        for (int j = 0; j < JT; j++)
            #pragma unroll
            for (int q = 0; q < 4; q++) acc[i][j][q] = 0.f;

    // one chunk = (128 + WROWS) rows x 8 x 16B
    auto issue_chunk = [&](int c, int stage) {
        const int k0 = c * BK;
        constexpr int NITER = (128 + WROWS) * 8 / 256;
        #pragma unroll
        for (int t = 0; t < NITER; t++) {
            int idx = tid + t * 256;
            uint32_t dst;
            const __half* gp;
            if (idx < 1024) {
                int r = idx >> 3, cc = idx & 7;
                gp = Abase + (size_t)r * CDIM + k0 + cc * 8;
                dst = sb + stage * GSTG + r * ROWB + cc * 16;
            } else {
                int w = idx - 1024;
                int r = w >> 3, cc = w & 7;
                gp = Wbase + (size_t)r * CDIM + k0 + cc * 8;
                dst = sb + stage * GSTG + TILE_A + r * ROWB + cc * 16;
            }
            cp_async16(dst, gp);
        }
        cp_commit();
    };

    issue_chunk(0, 0);

    #pragma unroll 1
    for (int c = 0; c < NCHUNK; c++) {
        // chunk c+1 is issued AFTER this wait -> must complete ALL outstanding.
        asm volatile("cp.async.wait_group 0;" ::: "memory");
        __syncthreads();
        if (c + 1 < NCHUNK) issue_chunk(c + 1, (c + 1) & 1);

        const uint32_t stg = sb + (c & 1) * GSTG;
        const uint32_t aB = stg;
        const uint32_t bB = stg + TILE_A;

        #pragma unroll
        for (int ks = 0; ks < 4; ks++) {
            const int kbyte = ks * 32;

            uint32_t ah[2][4];
            {
                int arow = wm * 32 + (lane & 15);
                int koff = kbyte + ((lane >> 4) << 4);
                #pragma unroll
                for (int i = 0; i < 2; i++) {
                    uint32_t off = (uint32_t)((arow + i * 16) * ROWB + koff);
                    ldm_x4(ah[i], aB + off);
                }
            }

            uint32_t bh[JT][2];
            {
                int nrow_in = ((lane >> 4) << 3) + (lane & 7);
                int kadd = ((lane >> 3) & 1) * 16;
                #pragma unroll
                for (int p = 0; p < JT / 2; p++) {
                    int nrow = wn * (JT * 8) + p * 16 + nrow_in;
                    uint32_t off = (uint32_t)(nrow * ROWB + kbyte + kadd);
                    uint32_t r4[4];
                    ldm_x4(r4, bB + off);
                    bh[2 * p][0] = r4[0]; bh[2 * p][1] = r4[1];
                    bh[2 * p + 1][0] = r4[2]; bh[2 * p + 1][1] = r4[3];
                }
            }

            #pragma unroll
            for (int i = 0; i < 2; i++)
                #pragma unroll
                for (int j = 0; j < JT; j++)
                    mma_f16(acc[i][j], ah[i], bh[j]);
        }
    }

    const int g = lane >> 2;
    const int tq = lane & 3;
    #pragma unroll
    for (int i = 0; i < 2; i++) {
        #pragma unroll
        for (int j = 0; j < JT; j++) {
            int row = bm + wm * 32 + i * 16 + g;
            int col = bn + wn * (JT * 8) + j * 8 + tq * 2;
            if (mode == 0) {
                float b0 = bias ? bias[col] : 0.f;
                float b1 = bias ? bias[col + 1] : 0.f;
                float2 v0 = make_float2(acc[i][j][0] + b0, acc[i][j][1] + b1);
                float2 v1 = make_float2(acc[i][j][2] + b0, acc[i][j][3] + b1);
                *reinterpret_cast<float2*>(out32 + (size_t)row * CDIM + col) = v0;
                *reinterpret_cast<float2*>(out32 + (size_t)(row + 8) * CDIM + col) = v1;
            } else {
                uint32_t h0 = pack_f16(acc[i][j][0] * scale, acc[i][j][1] * scale);
                uint32_t h1 = pack_f16(acc[i][j][2] * scale, acc[i][j][3] * scale);
                *reinterpret_cast<uint32_t*>(outh + (size_t)row * CDIM + col) = h0;
                *reinterpret_cast<uint32_t*>(outh + (size_t)(row + 8) * CDIM + col) = h1;
            }
        }
    }
}

#define GEMM_SMEM_QKV (2 * (TILE_A + 128 * ROWB))   // 73728
#define GEMM_SMEM_OUT (2 * (TILE_A + 64 * ROWB))    // 55296

__global__ __launch_bounds__(256, 2) void gemm_qkv(
    const __half* __restrict__ x, const __half* __restrict__ y,
    const __half* __restrict__ wq, const __half* __restrict__ wk,
    const __half* __restrict__ wv,
    __half* __restrict__ qf, __half* __restrict__ kf, __half* __restrict__ vf)
{
    extern __shared__ char smem[];
    const int z = blockIdx.z;
    const __half* A = (z == 0) ? x : y;
    const __half* W = (z == 0) ? wq : (z == 1) ? wk : wv;
    __half* out     = (z == 0) ? qf : (z == 1) ? kf : vf;
    const float scale = (z == 0) ? SCALE_HOST : 1.0f;
    gemm_body<128>(A, W, nullptr, nullptr, out, scale, 1,
                   smem, blockIdx.x * BM, blockIdx.y * 128);
}

__global__ __launch_bounds__(256, 2) void gemm_out(
    const __half* __restrict__ A, const __half* __restrict__ W,
    const float* __restrict__ bias, float* __restrict__ out32)
{
    extern __shared__ char smem[];
    gemm_body<64>(A, W, bias, out32, nullptr, 1.0f, 0,
                  smem, blockIdx.x * BM, blockIdx.y * 64);
}

// ======================= tensor-core flash attention ========================
// Round-14 version (known optimum): 256 threads, 8 warps x 16 q-rows, KV=32,
// 4-stage single-sync pipeline, Q fragments register-resident.
#define AQ 128
#define AK 32
#define QROWB 208
#define NKV (NTOK / AK)          // 32
#define SQ_BYTES (AQ * QROWB)    // 26624
#define KV_BYTES (AK * QROWB)    // 6656
#define ASTG (2 * KV_BYTES)      // 13312 (K, V)
#define ATTN_SMEM (SQ_BYTES + 4 * ASTG)  // 79872

__global__ __launch_bounds__(256, 2) void attn_mma(
    const __half* __restrict__ Q_g,
    const __half* __restrict__ K_g,
    const __half* __restrict__ V_g,
    const float* __restrict__ relpos,
    __half* __restrict__ O_g)
{
    extern __shared__ char smem[];
    const uint32_t sb = smem_u32(smem);
    const int tid = threadIdx.x;
    const int lane = tid & 31;
    const int w = tid >> 5;
    const int g = lane >> 2;
    const int tq = lane & 3;
    const int bh = blockIdx.y;
    const int b = bh >> 3;
    const int h = bh & 7;
    const int q0 = blockIdx.x * AQ;

    const uint32_t sQ = sb;
    const uint32_t sStage = sb + SQ_BYTES;

    const uint32_t ones_b[2] = { (g == 0) ? 0x3C003C00u : 0u,
                                 (g == 0) ? 0x3C003C00u : 0u };

    {
        const size_t qb = ((size_t)(b * NTOK + q0)) * CDIM + h * HD;
        #pragma unroll
        for (int t = 0; t < 6; t++) {
            int idx = t * 256 + tid;
            int r = idx / 12, c = idx % 12;
            uint32_t o = (uint32_t)(r * QROWB + c * 16);
            cp_async16(sQ + o, Q_g + qb + (size_t)r * CDIM + c * 8);
        }
        cp_commit();
    }

    auto load_kv = [&](int kt, int s) {
        const size_t base = ((size_t)(b * NTOK + kt * AK)) * CDIM + h * HD;
        uint32_t st = sStage + s * ASTG;
        #pragma unroll
        for (int t = 0; t < 2; t++) {
            int idx = t * 256 + tid;
            if (idx < AK * 12) {
                int r = idx / 12, c = idx % 12;
                uint32_t o = (uint32_t)(r * QROWB + c * 16);
                const size_t go = base + (size_t)r * CDIM + c * 8;
                cp_async16(st + o,            K_g + go);
                cp_async16(st + KV_BYTES + o, V_g + go);
            }
        }
        cp_commit();
    };

    load_kv(0, 0);
    load_kv(1, 1);
    load_kv(2, 2);

    asm volatile("cp.async.wait_group 3;" ::: "memory");
    __syncthreads();

    uint32_t qreg[6][4];
    {
        const uint32_t aoff = (uint32_t)((w * 16 + (lane & 15)) * QROWB + ((lane >> 4) << 4));
        #pragma unroll
        for (int t = 0; t < 6; t++)
            ldm_x4(qreg[t], sQ + aoff + t * 32);
    }

    float o[12][4];
    float ol[4];
    #pragma unroll
    for (int u = 0; u < 12; u++)
        #pragma unroll
        for (int q = 0; q < 4; q++) o[u][q] = 0.f;
    #pragma unroll
    for (int q = 0; q < 4; q++) ol[q] = 0.f;

    const float* rpbase = relpos + ((size_t)h * NTOK + q0 + w * 16 + g) * NTOK + tq * 2;

    #pragma unroll 1
    for (int kt = 0; kt < NKV; kt++) {
        cp_wait_n(NKV - 1 - kt);
        __syncthreads();
        if (kt + 3 < NKV) load_kv(kt + 3, (kt + 3) & 3);

        const uint32_t stK = sStage + (kt & 3) * ASTG;
        const uint32_t stV = stK + KV_BYTES;

        float sc[4][4];
        #pragma unroll
        for (int j = 0; j < 4; j++)
            #pragma unroll
            for (int q = 0; q < 4; q++) sc[j][q] = 0.f;

        {
            const int nr = ((lane >> 4) << 3) + (lane & 7);
            const uint32_t kadd = ((lane >> 3) & 1) << 4;
            #pragma unroll
            for (int t = 0; t < 6; t++) {
                #pragma unroll
                for (int p = 0; p < 2; p++) {
                    uint32_t off = (uint32_t)((16 * p + nr) * QROWB + t * 32 + kadd);
                    uint32_t kh[4];
                    ldm_x4(kh, stK + off);
                    mma_f16(sc[2 * p], qreg[t], kh);
                    mma_f16(sc[2 * p + 1], qreg[t], kh + 2);
                }
            }
        }

        const float* rpb = rpbase + kt * AK;
        float2 rp0[4], rp1[4];
        #pragma unroll
        for (int j = 0; j < 4; j++) {
            rp0[j] = *reinterpret_cast<const float2*>(rpb + (size_t)j * 8);
            rp1[j] = *reinterpret_cast<const float2*>(rpb + 8 * (size_t)NTOK + (size_t)j * 8);
        }

        uint32_t pe[4][2];
        #pragma unroll
        for (int j = 0; j < 4; j++) {
            float t0 = (sc[j][0] + rp0[j].x) * LOG2E - SOFT_SHIFT * LOG2E;
            float t1 = (sc[j][1] + rp0[j].y) * LOG2E - SOFT_SHIFT * LOG2E;
            float t2 = (sc[j][2] + rp1[j].x) * LOG2E - SOFT_SHIFT * LOG2E;
            float t3 = (sc[j][3] + rp1[j].y) * LOG2E - SOFT_SHIFT * LOG2E;
            pe[j][0] = exp2_pack(t0, t1);
            pe[j][1] = exp2_pack(t2, t3);
        }

        {
            const int vrow_in = ((lane >> 3) & 1) * 8 + (lane & 7);
            const uint32_t vcb = (uint32_t)((lane >> 4) << 4);
            #pragma unroll
            for (int t = 0; t < 2; t++) {
                uint32_t pa[4];
                pa[0] = pe[2 * t][0];
                pa[1] = pe[2 * t][1];
                pa[2] = pe[2 * t + 1][0];
                pa[3] = pe[2 * t + 1][1];
                mma_f16(ol, pa, ones_b);
                const uint32_t vro = (uint32_t)((16 * t + vrow_in) * QROWB) + vcb;
                #pragma unroll
                for (int u = 0; u < 6; u++) {
                    uint32_t off = vro + u * 32;
                    uint32_t vh[4];
                    ldm_x4_t(vh, stV + off);
                    mma_f16(o[2 * u], pa, vh);
                    mma_f16(o[2 * u + 1], pa, vh + 2);
                }
            }
        }
    }

    float l0 = __shfl_sync(0xffffffffu, ol[0], lane & 28);
    float l1 = __shfl_sync(0xffffffffu, ol[2], lane & 28);
    const float i0 = 1.f / l0, i1 = 1.f / l1;

    const size_t r0 = (size_t)(b * NTOK + q0 + w * 16 + g) * CDIM;
    const size_t r1 = r0 + 8 * CDIM;
    #pragma unroll
    for (int u = 0; u < 12; u++) {
        const int col = h * HD + u * 8 + tq * 2;
        *reinterpret_cast<uint32_t*>(O_g + r0 + col) =
            pack_f16(o[u][0] * i0, o[u][1] * i0);
        *reinterpret_cast<uint32_t*>(O_g + r1 + col) =
            pack_f16(o[u][2] * i1, o[u][3] * i1);
    }
}

// ---------------- launch ----------------------------------------------------
extern "C" void kernel_launch(void* const* d_in, const int* in_sizes, int n_in,
                              void* d_out, int out_size)
{
    const float* x      = (const float*)d_in[0];
    const float* y      = (const float*)d_in[1];
    const float* relpos = (const float*)d_in[2];
    const float* Wq = (const float*)d_in[5];
    const float* Wk = (const float*)d_in[6];
    const float* Wv = (const float*)d_in[7];
    const float* Wp = (const float*)d_in[8];
    const float* bp = (const float*)d_in[9];
    float* out = (float*)d_out;

    __half *xf, *yf, *qf, *kf, *vf, *of;
    __half *wq, *wk, *wv, *wp;
    cudaGetSymbolAddress((void**)&xf, g_xf16);
    cudaGetSymbolAddress((void**)&yf, g_yf16);
    cudaGetSymbolAddress((void**)&qf, g_qf16);
    cudaGetSymbolAddress((void**)&kf, g_kf16);
    cudaGetSymbolAddress((void**)&vf, g_vf16);
    cudaGetSymbolAddress((void**)&of, g_of16);
    cudaGetSymbolAddress((void**)&wq, g_wq);
    cudaGetSymbolAddress((void**)&wk, g_wk);
    cudaGetSymbolAddress((void**)&wv, g_wv);
    cudaGetSymbolAddress((void**)&wp, g_wp);

    const int nBig4 = MROWS * CDIM / 4;
    const int nW4   = CDIM * CDIM / 4;

    {
        dim3 gz((nBig4 + 255) / 256, 1, 2);
        convert_f16_multi<<<gz, 256>>>(x, xf, y, yf, nullptr, nullptr,
                                       nullptr, nullptr, nBig4);
        dim3 gw((nW4 + 255) / 256, 1, 4);
        convert_f16_multi<<<gw, 256>>>(Wq, wq, Wk, wk, Wv, wv, Wp, wp, nW4);
    }

    cudaFuncSetAttribute(gemm_qkv, cudaFuncAttributeMaxDynamicSharedMemorySize, GEMM_SMEM_QKV);
    cudaFuncSetAttribute(gemm_out, cudaFuncAttributeMaxDynamicSharedMemorySize, GEMM_SMEM_OUT);

    dim3 gqkv(MROWS / BM, CDIM / 128, 3);   // (64, 6, 3) = 1152 CTAs
    gemm_qkv<<<gqkv, 256, GEMM_SMEM_QKV>>>(xf, yf, wq, wk, wv, qf, kf, vf);

    cudaFuncSetAttribute(attn_mma, cudaFuncAttributeMaxDynamicSharedMemorySize, ATTN_SMEM);
    dim3 agrid(NTOK / AQ, BATCH * HEADS);   // (8, 64)
    attn_mma<<<agrid, 256, ATTN_SMEM>>>(qf, kf, vf, relpos, of);

    dim3 gout(MROWS / BM, CDIM / 64);       // (64, 12) = 768 CTAs, finer waves
    gemm_out<<<gout, 256, GEMM_SMEM_OUT>>>(of, wp, bp, out);
}

// round 17
// speedup vs baseline: 1.0733x; 1.0028x over previous
#include <cuda_runtime.h>
#include <cuda_bf16.h>
#include <cuda_fp16.h>
#include <math.h>
#include <stdint.h>

// Problem constants
#define BATCH 8
#define NTOK 1024
#define CDIM 768
#define HEADS 8
#define HD 96
#define MROWS (BATCH * NTOK)   // 8192
#define SCALE_HOST 0.10206207261596577f
#define LOG2E 1.4426950408889634f
#define SOFT_SHIFT 4.0f

// ---------------- scratch (device globals; no allocation allowed) ----------
__device__ __align__(16) __half g_xf16[MROWS * CDIM];
__device__ __align__(16) __half g_yf16[MROWS * CDIM];
__device__ __align__(16) __half g_qf16[MROWS * CDIM];
__device__ __align__(16) __half g_kf16[MROWS * CDIM];
__device__ __align__(16) __half g_vf16[MROWS * CDIM];
__device__ __align__(16) __half g_of16[MROWS * CDIM];
__device__ __align__(16) __half g_wq[CDIM * CDIM];
__device__ __align__(16) __half g_wk[CDIM * CDIM];
__device__ __align__(16) __half g_wv[CDIM * CDIM];
__device__ __align__(16) __half g_wp[CDIM * CDIM];

// ======================= small PTX helpers ===================================
__device__ __forceinline__ uint32_t smem_u32(const void* p) {
    uint32_t a;
    asm("{ .reg .u64 t; cvta.to.shared.u64 t, %1; cvt.u32.u64 %0, t; }"
        : "=r"(a) : "l"(p));
    return a;
}
__device__ __forceinline__ void cp_async16(uint32_t saddr, const void* gaddr) {
    asm volatile("cp.async.cg.shared.global [%0], [%1], 16;"
                 :: "r"(saddr), "l"(gaddr) : "memory");
}
__device__ __forceinline__ void cp_commit() {
    asm volatile("cp.async.commit_group;" ::: "memory");
}
__device__ __forceinline__ void cp_wait_n(int rem) {
    if (rem >= 2)      asm volatile("cp.async.wait_group 2;" ::: "memory");
    else if (rem == 1) asm volatile("cp.async.wait_group 1;" ::: "memory");
    else               asm volatile("cp.async.wait_group 0;" ::: "memory");
}
__device__ __forceinline__ void ldm_x4(uint32_t* r, uint32_t addr) {
    asm volatile("ldmatrix.sync.aligned.m8n8.x4.shared.b16 {%0,%1,%2,%3}, [%4];"
                 : "=r"(r[0]), "=r"(r[1]), "=r"(r[2]), "=r"(r[3]) : "r"(addr));
}
__device__ __forceinline__ void ldm_x4_t(uint32_t* r, uint32_t addr) {
    asm volatile("ldmatrix.sync.aligned.m8n8.x4.trans.shared.b16 {%0,%1,%2,%3}, [%4];"
                 : "=r"(r[0]), "=r"(r[1]), "=r"(r[2]), "=r"(r[3]) : "r"(addr));
}
__device__ __forceinline__ void mma_f16(float* c, const uint32_t* a, const uint32_t* b) {
    asm volatile(
        "mma.sync.aligned.m16n8k16.row.col.f32.f16.f16.f32 "
        "{%0,%1,%2,%3}, {%4,%5,%6,%7}, {%8,%9}, {%0,%1,%2,%3};"
        : "+f"(c[0]), "+f"(c[1]), "+f"(c[2]), "+f"(c[3])
        : "r"(a[0]), "r"(a[1]), "r"(a[2]), "r"(a[3]), "r"(b[0]), "r"(b[1]));
}
__device__ __forceinline__ uint32_t pack_f16(float a, float b) {
    uint32_t r;
    asm("cvt.rn.f16x2.f32 %0, %2, %1;" : "=r"(r) : "f"(a), "f"(b));
    return r;
}
__device__ __forceinline__ uint32_t exp2_pack(float t0, float t1) {
    float p0, p1;
    asm("ex2.approx.f32 %0, %1;" : "=f"(p0) : "f"(t0));
    asm("ex2.approx.f32 %0, %1;" : "=f"(p1) : "f"(t1));
    return pack_f16(p0, p1);
}

// ======================= single fused convert ================================
// z = 0,1: big tensors (x,y) with nBig4 elements; z = 2..5: weights with nW4.
__global__ void convert_all(const float* __restrict__ s0, __half* __restrict__ d0,
                            const float* __restrict__ s1, __half* __restrict__ d1,
                            const float* __restrict__ s2, __half* __restrict__ d2,
                            const float* __restrict__ s3, __half* __restrict__ d3,
                            const float* __restrict__ s4, __half* __restrict__ d4,
                            const float* __restrict__ s5, __half* __restrict__ d5,
                            int nBig4, int nW4)
{
    int i = blockIdx.x * blockDim.x + threadIdx.x;
    const int z = blockIdx.z;
    const int n = (z < 2) ? nBig4 : nW4;
    if (i >= n) return;
    const float* src;
    __half* dst;
    switch (z) {
        case 0: src = s0; dst = d0; break;
        case 1: src = s1; dst = d1; break;
        case 2: src = s2; dst = d2; break;
        case 3: src = s3; dst = d3; break;
        case 4: src = s4; dst = d4; break;
        default: src = s5; dst = d5; break;
    }
    float4 v = reinterpret_cast<const float4*>(src)[i];
    uint32_t h0 = pack_f16(v.x, v.y);
    uint32_t h1 = pack_f16(v.z, v.w);
    reinterpret_cast<uint2*>(dst)[i] = make_uint2(h0, h1);
}

// ======================= 1-pass f16 GEMM (BK=64, 2-stage, BN=128) ============
#define BM 128
#define BN 128
#define BK 64
#define NCHUNK (CDIM / BK)       // 12
#define ROWB 144                 // 64 f16 = 128B + 16B pad
#define TILE_SZ (128 * ROWB)     // 18432
#define GSTG (2 * TILE_SZ)       // 36864 per stage (A, W)
#define GEMM_SMEM (2 * GSTG)     // 73728

__device__ __forceinline__ void gemm_body(
    const __half* __restrict__ A, const __half* __restrict__ W,
    const float* __restrict__ bias, float* __restrict__ out32,
    __half* __restrict__ outh, float scale, int mode,
    char* smem, int bm, int bn)
{
    const uint32_t sb = smem_u32(smem);
    const int tid = threadIdx.x;
    const int wid = tid >> 5;
    const int lane = tid & 31;
    const int wm = wid >> 1;
    const int wn = wid & 1;

    const __half* gbase[2];
    gbase[0] = A + (size_t)bm * CDIM;
    gbase[1] = W + (size_t)bn * CDIM;

    float acc[2][8][4];
    #pragma unroll
    for (int i = 0; i < 2; i++)
        #pragma unroll
        for (int j = 0; j < 8; j++)
            #pragma unroll
            for (int q = 0; q < 4; q++) acc[i][j][q] = 0.f;

    auto issue_chunk = [&](int c, int stage) {
        const int k0 = c * BK;
        #pragma unroll
        for (int t = 0; t < 8; t++) {
            int idx = tid + t * 256;          // 0..2047
            int tile = idx >> 10;
            int w = idx & 1023;
            int r = w >> 3, cc = w & 7;
            const __half* gp = gbase[tile] + (size_t)r * CDIM + k0 + cc * 8;
            uint32_t dst = sb + stage * GSTG + tile * TILE_SZ + r * ROWB + cc * 16;
            cp_async16(dst, gp);
        }
        cp_commit();
    };

    issue_chunk(0, 0);

    #pragma unroll 1
    for (int c = 0; c < NCHUNK; c++) {
        // chunk c+1 is issued AFTER this wait -> must drain ALL outstanding.
        asm volatile("cp.async.wait_group 0;" ::: "memory");
        __syncthreads();
        if (c + 1 < NCHUNK) issue_chunk(c + 1, (c + 1) & 1);

        const uint32_t stg = sb + (c & 1) * GSTG;
        const uint32_t aB = stg;
        const uint32_t bB = stg + TILE_SZ;

        #pragma unroll
        for (int ks = 0; ks < 4; ks++) {
            const int kbyte = ks * 32;

            uint32_t ah[2][4];
            {
                int arow = wm * 32 + (lane & 15);
                int koff = kbyte + ((lane >> 4) << 4);
                #pragma unroll
                for (int i = 0; i < 2; i++) {
                    uint32_t off = (uint32_t)((arow + i * 16) * ROWB + koff);
                    ldm_x4(ah[i], aB + off);
                }
            }

            uint32_t bh[8][2];
            {
                int nrow_in = ((lane >> 4) << 3) + (lane & 7);
                int kadd = ((lane >> 3) & 1) * 16;
                #pragma unroll
                for (int p = 0; p < 4; p++) {
                    int nrow = wn * 64 + p * 16 + nrow_in;
                    uint32_t off = (uint32_t)(nrow * ROWB + kbyte + kadd);
                    uint32_t r4[4];
                    ldm_x4(r4, bB + off);
                    bh[2 * p][0] = r4[0]; bh[2 * p][1] = r4[1];
                    bh[2 * p + 1][0] = r4[2]; bh[2 * p + 1][1] = r4[3];
                }
            }

            #pragma unroll
            for (int i = 0; i < 2; i++)
                #pragma unroll
                for (int j = 0; j < 8; j++)
                    mma_f16(acc[i][j], ah[i], bh[j]);
        }
    }

    const int g = lane >> 2;
    const int tq = lane & 3;
    #pragma unroll
    for (int i = 0; i < 2; i++) {
        #pragma unroll
        for (int j = 0; j < 8; j++) {
            int row = bm + wm * 32 + i * 16 + g;
            int col = bn + wn * 64 + j * 8 + tq * 2;
            if (mode == 0) {
                float b0 = bias ? bias[col] : 0.f;
                float b1 = bias ? bias[col + 1] : 0.f;
                float2 v0 = make_float2(acc[i][j][0] + b0, acc[i][j][1] + b1);
                float2 v1 = make_float2(acc[i][j][2] + b0, acc[i][j][3] + b1);
                *reinterpret_cast<float2*>(out32 + (size_t)row * CDIM + col) = v0;
                *reinterpret_cast<float2*>(out32 + (size_t)(row + 8) * CDIM + col) = v1;
            } else {
                uint32_t h0 = pack_f16(acc[i][j][0] * scale, acc[i][j][1] * scale);
                uint32_t h1 = pack_f16(acc[i][j][2] * scale, acc[i][j][3] * scale);
                *reinterpret_cast<uint32_t*>(outh + (size_t)row * CDIM + col) = h0;
                *reinterpret_cast<uint32_t*>(outh + (size_t)(row + 8) * CDIM + col) = h1;
            }
        }
    }
}

__global__ __launch_bounds__(256, 2) void gemm_qkv(
    const __half* __restrict__ x, const __half* __restrict__ y,
    const __half* __restrict__ wq, const __half* __restrict__ wk,
    const __half* __restrict__ wv,
    __half* __restrict__ qf, __half* __restrict__ kf, __half* __restrict__ vf)
{
    extern __shared__ char smem[];
    const int z = blockIdx.z;
    const __half* A = (z == 0) ? x : y;
    const __half* W = (z == 0) ? wq : (z == 1) ? wk : wv;
    __half* out     = (z == 0) ? qf : (z == 1) ? kf : vf;
    const float scale = (z == 0) ? SCALE_HOST : 1.0f;
    gemm_body(A, W, nullptr, nullptr, out, scale, 1,
              smem, blockIdx.x * BM, blockIdx.y * BN);
}

__global__ __launch_bounds__(256, 2) void gemm_out(
    const __half* __restrict__ A, const __half* __restrict__ W,
    const float* __restrict__ bias, float* __restrict__ out32)
{
    extern __shared__ char smem[];
    gemm_body(A, W, bias, out32, nullptr, 1.0f, 0,
              smem, blockIdx.x * BM, blockIdx.y * BN);
}

// ======================= tensor-core flash attention ========================
// Round-14 configuration (measured optimum): 256 threads, 8 warps x 16 q-rows,
// KV tiles of 32, 4-stage single-sync pipeline, Q fragments register-resident.
#define AQ 128
#define AK 32
#define QROWB 208
#define NKV (NTOK / AK)          // 32
#define SQ_BYTES (AQ * QROWB)    // 26624
#define KV_BYTES (AK * QROWB)    // 6656
#define ASTG (2 * KV_BYTES)      // 13312 (K, V)
#define ATTN_SMEM (SQ_BYTES + 4 * ASTG)  // 79872

__global__ __launch_bounds__(256, 2) void attn_mma(
    const __half* __restrict__ Q_g,
    const __half* __restrict__ K_g,
    const __half* __restrict__ V_g,
    const float* __restrict__ relpos,
    __half* __restrict__ O_g)
{
    extern __shared__ char smem[];
    const uint32_t sb = smem_u32(smem);
    const int tid = threadIdx.x;
    const int lane = tid & 31;
    const int w = tid >> 5;
    const int g = lane >> 2;
    const int tq = lane & 3;
    const int bh = blockIdx.y;
    const int b = bh >> 3;
    const int h = bh & 7;
    const int q0 = blockIdx.x * AQ;

    const uint32_t sQ = sb;
    const uint32_t sStage = sb + SQ_BYTES;

    const uint32_t ones_b[2] = { (g == 0) ? 0x3C003C00u : 0u,
                                 (g == 0) ? 0x3C003C00u : 0u };

    {
        const size_t qb = ((size_t)(b * NTOK + q0)) * CDIM + h * HD;
        #pragma unroll
        for (int t = 0; t < 6; t++) {
            int idx = t * 256 + tid;
            int r = idx / 12, c = idx % 12;
            uint32_t o = (uint32_t)(r * QROWB + c * 16);
            cp_async16(sQ + o, Q_g + qb + (size_t)r * CDIM + c * 8);
        }
        cp_commit();
    }

    auto load_kv = [&](int kt, int s) {
        const size_t base = ((size_t)(b * NTOK + kt * AK)) * CDIM + h * HD;
        uint32_t st = sStage + s * ASTG;
        #pragma unroll
        for (int t = 0; t < 2; t++) {
            int idx = t * 256 + tid;
            if (idx < AK * 12) {
                int r = idx / 12, c = idx % 12;
                uint32_t o = (uint32_t)(r * QROWB + c * 16);
                const size_t go = base + (size_t)r * CDIM + c * 8;
                cp_async16(st + o,            K_g + go);
                cp_async16(st + KV_BYTES + o, V_g + go);
            }
        }
        cp_commit();
    };

    load_kv(0, 0);
    load_kv(1, 1);
    load_kv(2, 2);

    asm volatile("cp.async.wait_group 3;" ::: "memory");
    __syncthreads();

    uint32_t qreg[6][4];
    {
        const uint32_t aoff = (uint32_t)((w * 16 + (lane & 15)) * QROWB + ((lane >> 4) << 4));
        #pragma unroll
        for (int t = 0; t < 6; t++)
            ldm_x4(qreg[t], sQ + aoff + t * 32);
    }

    float o[12][4];
    float ol[4];
    #pragma unroll
    for (int u = 0; u < 12; u++)
        #pragma unroll
        for (int q = 0; q < 4; q++) o[u][q] = 0.f;
    #pragma unroll
    for (int q = 0; q < 4; q++) ol[q] = 0.f;

    const float* rpbase = relpos + ((size_t)h * NTOK + q0 + w * 16 + g) * NTOK + tq * 2;

    #pragma unroll 1
    for (int kt = 0; kt < NKV; kt++) {
        cp_wait_n(NKV - 1 - kt);
        __syncthreads();
        if (kt + 3 < NKV) load_kv(kt + 3, (kt + 3) & 3);

        const uint32_t stK = sStage + (kt & 3) * ASTG;
        const uint32_t stV = stK + KV_BYTES;

        float sc[4][4];
        #pragma unroll
        for (int j = 0; j < 4; j++)
            #pragma unroll
            for (int q = 0; q < 4; q++) sc[j][q] = 0.f;

        {
            const int nr = ((lane >> 4) << 3) + (lane & 7);
            const uint32_t kadd = ((lane >> 3) & 1) << 4;
            #pragma unroll
            for (int t = 0; t < 6; t++) {
                #pragma unroll
                for (int p = 0; p < 2; p++) {
                    uint32_t off = (uint32_t)((16 * p + nr) * QROWB + t * 32 + kadd);
                    uint32_t kh[4];
                    ldm_x4(kh, stK + off);
                    mma_f16(sc[2 * p], qreg[t], kh);
                    mma_f16(sc[2 * p + 1], qreg[t], kh + 2);
                }
            }
        }

        const float* rpb = rpbase + kt * AK;
        float2 rp0[4], rp1[4];
        #pragma unroll
        for (int j = 0; j < 4; j++) {
            rp0[j] = *reinterpret_cast<const float2*>(rpb + (size_t)j * 8);
            rp1[j] = *reinterpret_cast<const float2*>(rpb + 8 * (size_t)NTOK + (size_t)j * 8);
        }

        uint32_t pe[4][2];
        #pragma unroll
        for (int j = 0; j < 4; j++) {
            float t0 = (sc[j][0] + rp0[j].x) * LOG2E - SOFT_SHIFT * LOG2E;
            float t1 = (sc[j][1] + rp0[j].y) * LOG2E - SOFT_SHIFT * LOG2E;
            float t2 = (sc[j][2] + rp1[j].x) * LOG2E - SOFT_SHIFT * LOG2E;
            float t3 = (sc[j][3] + rp1[j].y) * LOG2E - SOFT_SHIFT * LOG2E;
            pe[j][0] = exp2_pack(t0, t1);
            pe[j][1] = exp2_pack(t2, t3);
        }

        {
            const int vrow_in = ((lane >> 3) & 1) * 8 + (lane & 7);
            const uint32_t vcb = (uint32_t)((lane >> 4) << 4);
            #pragma unroll
            for (int t = 0; t < 2; t++) {
                uint32_t pa[4];
                pa[0] = pe[2 * t][0];
                pa[1] = pe[2 * t][1];
                pa[2] = pe[2 * t + 1][0];
                pa[3] = pe[2 * t + 1][1];
                mma_f16(ol, pa, ones_b);
                const uint32_t vro = (uint32_t)((16 * t + vrow_in) * QROWB) + vcb;
                #pragma unroll
                for (int u = 0; u < 6; u++) {
                    uint32_t off = vro + u * 32;
                    uint32_t vh[4];
                    ldm_x4_t(vh, stV + off);
                    mma_f16(o[2 * u], pa, vh);
                    mma_f16(o[2 * u + 1], pa, vh + 2);
                }
            }
        }
    }

    float l0 = __shfl_sync(0xffffffffu, ol[0], lane & 28);
    float l1 = __shfl_sync(0xffffffffu, ol[2], lane & 28);
    const float i0 = 1.f / l0, i1 = 1.f / l1;

    const size_t r0 = (size_t)(b * NTOK + q0 + w * 16 + g) * CDIM;
    const size_t r1 = r0 + 8 * CDIM;
    #pragma unroll
    for (int u = 0; u < 12; u++) {
        const int col = h * HD + u * 8 + tq * 2;
        *reinterpret_cast<uint32_t*>(O_g + r0 + col) =
            pack_f16(o[u][0] * i0, o[u][1] * i0);
        *reinterpret_cast<uint32_t*>(O_g + r1 + col) =
            pack_f16(o[u][2] * i1, o[u][3] * i1);
    }
}

// ---------------- launch ----------------------------------------------------
extern "C" void kernel_launch(void* const* d_in, const int* in_sizes, int n_in,
                              void* d_out, int out_size)
{
    const float* x      = (const float*)d_in[0];
    const float* y      = (const float*)d_in[1];
    const float* relpos = (const float*)d_in[2];
    const float* Wq = (const float*)d_in[5];
    const float* Wk = (const float*)d_in[6];
    const float* Wv = (const float*)d_in[7];
    const float* Wp = (const float*)d_in[8];
    const float* bp = (const float*)d_in[9];
    float* out = (float*)d_out;

    __half *xf, *yf, *qf, *kf, *vf, *of;
    __half *wq, *wk, *wv, *wp;
    cudaGetSymbolAddress((void**)&xf, g_xf16);
    cudaGetSymbolAddress((void**)&yf, g_yf16);
    cudaGetSymbolAddress((void**)&qf, g_qf16);
    cudaGetSymbolAddress((void**)&kf, g_kf16);
    cudaGetSymbolAddress((void**)&vf, g_vf16);
    cudaGetSymbolAddress((void**)&of, g_of16);
    cudaGetSymbolAddress((void**)&wq, g_wq);
    cudaGetSymbolAddress((void**)&wk, g_wk);
    cudaGetSymbolAddress((void**)&wv, g_wv);
    cudaGetSymbolAddress((void**)&wp, g_wp);

    const int nBig4 = MROWS * CDIM / 4;   // 1572864
    const int nW4   = CDIM * CDIM / 4;    // 147456

    // single fused convert launch: z=0,1 -> x,y ; z=2..5 -> Wq,Wk,Wv,Wp
    {
        dim3 gc((nBig4 + 255) / 256, 1, 6);
        convert_all<<<gc, 256>>>(x, xf, y, yf,
                                 Wq, wq, Wk, wk, Wv, wv, Wp, wp,
                                 nBig4, nW4);
    }

    cudaFuncSetAttribute(gemm_qkv, cudaFuncAttributeMaxDynamicSharedMemorySize, GEMM_SMEM);
    cudaFuncSetAttribute(gemm_out, cudaFuncAttributeMaxDynamicSharedMemorySize, GEMM_SMEM);

    dim3 gqkv(MROWS / BM, CDIM / BN, 3);   // (64, 6, 3) = 1152 CTAs
    gemm_qkv<<<gqkv, 256, GEMM_SMEM>>>(xf, yf, wq, wk, wv, qf, kf, vf);

    cudaFuncSetAttribute(attn_mma, cudaFuncAttributeMaxDynamicSharedMemorySize, ATTN_SMEM);
    dim3 agrid(NTOK / AQ, BATCH * HEADS);  // (8, 64)
    attn_mma<<<agrid, 256, ATTN_SMEM>>>(qf, kf, vf, relpos, of);

    dim3 gout(MROWS / BM, CDIM / BN);      // (64, 6)
    gemm_out<<<gout, 256, GEMM_SMEM>>>(of, wp, bp, out);
}